// round 7
// baseline (speedup 1.0000x reference)
#include <cuda_runtime.h>
#include <cuda_bf16.h>
#include <mma.h>
#include <math.h>

using namespace nvcuda;

// Problem constants
#define TT 16
#define INDIM 12288
#define HH1 256
#define HH2 512
#define BB 128
#define MROWS (TT * BB)          // 2048
#define BT 32                    // batch tile for recurrence kernels

// ---------------------------------------------------------------------------
// Device scratch (static allocation only — no cudaMalloc allowed)
// ---------------------------------------------------------------------------
__device__ float g_pre1 [MROWS * 4 * HH1];   // 8 MB
__device__ float g_pre2 [MROWS * 4 * HH2];   // 16 MB
__device__ float g_y1   [MROWS * HH1];       // 2 MB  — layer-1 h history (tf32-rounded)
__device__ float g_y2t  [MROWS * HH2];       // 4 MB  — layer-2 h history (tf32-rounded)
__device__ float g_inpt [MROWS * INDIM];     // 96 MB — tf32-rounded input
__device__ float g_wih1t[4 * HH1 * INDIM];   // 48 MB — tf32-rounded Wih1
__device__ float g_wih2t[4 * HH2 * HH1];     // 4 MB  — tf32-rounded Wih2
__device__ int   g_ctr  [2];                 // grid-barrier counters

// ---------------------------------------------------------------------------
// cp.async helpers
// ---------------------------------------------------------------------------
__device__ __forceinline__ void cp_async16(void* smem_dst, const void* gmem_src) {
    unsigned saddr = (unsigned)__cvta_generic_to_shared(smem_dst);
    asm volatile("cp.async.cg.shared.global [%0], [%1], 16;\n"
                 :: "r"(saddr), "l"(gmem_src));
}
__device__ __forceinline__ void cp_async_commit() {
    asm volatile("cp.async.commit_group;\n" ::: "memory");
}
__device__ __forceinline__ void cp_async_wait1() {
    asm volatile("cp.async.wait_group 1;\n" ::: "memory");
}
__device__ __forceinline__ void cp_async_wait0() {
    asm volatile("cp.async.wait_group 0;\n" ::: "memory");
}

// Fast activations (MUFU-based; |gate| << 88 for this problem)
__device__ __forceinline__ float fast_sigmoid(float x) {
    return __fdividef(1.0f, 1.0f + __expf(-x));
}
__device__ __forceinline__ float fast_tanh(float x) {
    x = fminf(fmaxf(x, -15.0f), 15.0f);          // tanh(±15) == ±1 to fp32
    float e = __expf(2.0f * x);
    return __fdividef(e - 1.0f, e + 1.0f);
}

__device__ __forceinline__ float4 round4_tf32(float4 v) {
    v.x = wmma::__float_to_tf32(v.x);
    v.y = wmma::__float_to_tf32(v.y);
    v.z = wmma::__float_to_tf32(v.z);
    v.w = wmma::__float_to_tf32(v.w);
    return v;
}

// ---------------------------------------------------------------------------
// Elementwise RN-round to tf32 (fp32 container). Once per operand matrix —
// downstream HMMA truncation on already-tf32 values is the identity, so the
// GEMMs need no per-fragment conversion.
// ---------------------------------------------------------------------------
__global__ void round_tf32_kernel(const float4* __restrict__ src,
                                  float4* __restrict__ dst, int n4)
{
    int i = blockIdx.x * blockDim.x + threadIdx.x;
    if (i < n4) dst[i] = round4_tf32(src[i]);
}

// ---------------------------------------------------------------------------
// GEMM: C[M,N] = A[M,K] @ W[N,K]^T      (A, W already tf32-rounded)
// tf32 wmma, 128x128 block tile, KC=32, 3-stage cp.async pipeline.
// 256 threads = 8 warps as 4(m) x 2(n); warp computes 32x64 via 2x4 frags.
// Block (0,0) also resets the grid-barrier counters for the downstream
// persistent LSTM kernels (stream order guarantees visibility).
// ---------------------------------------------------------------------------
#define GEMM_LD 36
#define GEMM_SMEM_BYTES (6 * 128 * GEMM_LD * 4)      // 110592

__global__ void __launch_bounds__(256, 1)
gemm_tf32_kernel(const float* __restrict__ A,
                 const float* __restrict__ W,
                 float* __restrict__ C,
                 int M, int N, int K,
                 int* __restrict__ ctr_reset)
{
    constexpr int KC = 32;
    constexpr int LD = GEMM_LD;
    extern __shared__ float smem[];
    float* As[3] = { smem,            smem + 128 * LD,     smem + 2 * 128 * LD };
    float* Bs[3] = { smem + 3*128*LD, smem + 4 * 128 * LD, smem + 5 * 128 * LD };

    const int tid  = threadIdx.x;
    const int warp = tid >> 5;
    const int wm   = warp >> 1;
    const int wn   = warp & 1;
    const int m0   = blockIdx.y * 128;
    const int n0   = blockIdx.x * 128;

    if (blockIdx.x == 0 && blockIdx.y == 0 && tid < 2) ctr_reset[tid] = 0;

    const int lr = tid >> 3;                  // row 0..31 (stride 32 over 4 iters)
    const int lc = (tid & 7) * 4;             // col 0..28

    auto load_tiles = [&](int stage, int k0) {
#pragma unroll
        for (int i = 0; i < 4; i++) {
            int r = lr + i * 32;
            cp_async16(&As[stage][r * LD + lc],
                       &A[(size_t)(m0 + r) * K + k0 + lc]);
            cp_async16(&Bs[stage][r * LD + lc],
                       &W[(size_t)(n0 + r) * K + k0 + lc]);
        }
    };

    wmma::fragment<wmma::accumulator, 16, 16, 8, float> acc[2][4];
#pragma unroll
    for (int mi = 0; mi < 2; mi++)
#pragma unroll
        for (int ni = 0; ni < 4; ni++)
            wmma::fill_fragment(acc[mi][ni], 0.0f);

    const int kiters = K / KC;                // >= 2 for all our calls
    load_tiles(0, 0);
    cp_async_commit();
    load_tiles(1, KC);
    cp_async_commit();

    for (int it = 0; it < kiters; it++) {
        cp_async_wait1();                     // tile 'it' landed
        __syncthreads();                      // visible to all; stage (it+2)%3 free
        if (it + 2 < kiters) load_tiles((it + 2) % 3, (it + 2) * KC);
        cp_async_commit();                    // keep group indexing aligned
        const int cur = it % 3;

#pragma unroll
        for (int kk = 0; kk < KC; kk += 8) {
            wmma::fragment<wmma::matrix_a, 16, 16, 8, wmma::precision::tf32,
                           wmma::row_major> a[2];
            wmma::fragment<wmma::matrix_b, 16, 16, 8, wmma::precision::tf32,
                           wmma::col_major> b[4];
#pragma unroll
            for (int mi = 0; mi < 2; mi++)
                wmma::load_matrix_sync(a[mi], &As[cur][(wm * 32 + mi * 16) * LD + kk], LD);
#pragma unroll
            for (int ni = 0; ni < 4; ni++)
                wmma::load_matrix_sync(b[ni], &Bs[cur][(wn * 64 + ni * 16) * LD + kk], LD);
#pragma unroll
            for (int mi = 0; mi < 2; mi++)
#pragma unroll
                for (int ni = 0; ni < 4; ni++)
                    wmma::mma_sync(acc[mi][ni], a[mi], b[ni], acc[mi][ni]);
        }
    }
    __syncthreads();

#pragma unroll
    for (int mi = 0; mi < 2; mi++)
#pragma unroll
        for (int ni = 0; ni < 4; ni++)
            wmma::store_matrix_sync(
                &C[(size_t)(m0 + wm * 32 + mi * 16) * N + n0 + wn * 64 + ni * 16],
                acc[mi][ni], N, wmma::mem_row_major);
}

// ---------------------------------------------------------------------------
// Persistent LSTM layer kernel: one launch runs all TT steps for one layer.
// Block owns (16-wide j-slice, BT=32-wide b-slice); its 64 N-columns are the
// gathered gate rows {j, H+j, 2H+j, 3H+j}.
//  - Whh slice cached in smem once, RN-rounded to tf32 at fill.
//  - h history written tf32-rounded to hist_t (matmul input); raw h written
//    to hist only when the pointers differ (layer 2: hist = d_out).
//  - pre[t] slice prefetched into smem, overlapped with the h@Whh^T matmul.
//  - c state in registers; steps separated by a software grid barrier
//    (grid <= 128 blocks, 1 block/SM -> all wave-1 resident).
// grid: (H/16, B/BT), block: 256 threads (8 warps: 2m x 4n).
// ---------------------------------------------------------------------------
template <int H>
__global__ void __launch_bounds__(256, 1)
lstm_layer_kernel(const float* __restrict__ pre,     // [T][B][4H]
                  const float* __restrict__ Whh,     // [4H][H]
                  const float* __restrict__ bias,    // [4H]
                  float* __restrict__ hist,          // [T][B][H] raw h (output)
                  float* __restrict__ hist_t,        // [T][B][H] tf32 h (matmul in)
                  int* __restrict__ ctr)
{
    constexpr int KC  = 64;
    constexpr int LDA = KC + 4;     // 68
    constexpr int LDB = H + 4;
    constexpr int LDS = 68;
    extern __shared__ float sm[];
    float* Bsm   = sm;                          // 64 * LDB
    float* As0   = Bsm + 64 * LDB;              // BT * LDA
    float* As1   = As0 + BT * LDA;              // BT * LDA
    float* Stage = As1 + BT * LDA;              // BT * LDS
    float* PreS  = Stage + BT * LDS;            // BT * 64 (gate-major pre slice)
    float* Asb[2] = { As0, As1 };

    const int tid  = threadIdx.x;
    const int warp = tid >> 5;
    const int wm   = warp >> 2;                 // 0..1 -> m offset 16
    const int wn   = warp & 3;                  // 0..3 -> n offset 16
    const int j0   = blockIdx.x * 16;
    const int b0   = blockIdx.y * BT;
    const int nblocks = gridDim.x * gridDim.y;

    // --- Cache Whh slice, RN-rounded to tf32 at fill ---
    for (int idx = tid; idx < 64 * (H / 4); idx += 256) {
        int r  = idx / (H / 4);
        int c4 = (idx % (H / 4)) * 4;
        int g = r >> 4, jj = r & 15;
        float4 v = *(const float4*)&Whh[(size_t)(g * H + j0 + jj) * H + c4];
        *(float4*)&Bsm[r * LDB + c4] = round4_tf32(v);
    }

    // --- Epilogue mapping (threads 0..127): bl = tid>>2, 4 consecutive j ---
    const int bl = tid >> 2;                    // 0..31 (for tid < 128)
    const int jq = (tid & 3) * 4;               // 0,4,8,12
    const int jg = j0 + jq;                     // global j of first output

    float4 breg[4];
    if (tid < 128) {
        breg[0] = *(const float4*)&bias[        jg];
        breg[1] = *(const float4*)&bias[H     + jg];
        breg[2] = *(const float4*)&bias[2 * H + jg];
        breg[3] = *(const float4*)&bias[3 * H + jg];
    }

    float creg[4] = { 0.f, 0.f, 0.f, 0.f };     // c state, thread-private
    __syncthreads();                             // Bsm ready

    auto load_A = [&](int stage, const float* hin, int k0) {
        // BT x KC floats = 512 float4, 2 per thread
#pragma unroll
        for (int i = 0; i < 2; i++) {
            int idx = tid + i * 256;
            int r  = idx >> 4;                  // 0..31
            int c4 = (idx & 15) * 4;
            cp_async16(&Asb[stage][r * LDA + c4], &hin[(b0 + r) * H + k0 + c4]);
        }
    };

    // Prefetch pre[t] slice into PreS (gate-major: PreS[bl][g*16+jj]).
    auto load_pre = [&](const float* pre_t) {
#pragma unroll
        for (int i = 0; i < 2; i++) {
            int idx = tid + i * 256;
            int r  = idx >> 4;                  // row 0..31
            int gq = (idx >> 2) & 3;            // gate 0..3
            int q  = (idx & 3) * 4;             // quad offset within 16 j
            cp_async16(&PreS[r * 64 + gq * 16 + q],
                       &pre_t[(size_t)(b0 + r) * 4 * H + gq * H + j0 + q]);
        }
    };

    for (int t = 0; t < TT; t++) {
        const float* pre_t = pre + (size_t)t * BB * 4 * H;
        wmma::fragment<wmma::accumulator, 16, 16, 8, float> acc;
        wmma::fill_fragment(acc, 0.0f);

        if (t > 0) {                             // h0 == 0 -> skip matmul at t=0
            const float* hin = hist_t + (size_t)(t - 1) * BB * H;
            constexpr int nch = H / KC;
            load_pre(pre_t);                     // rides group 0 with A-chunk 0
            load_A(0, hin, 0);
            cp_async_commit();
#pragma unroll
            for (int ch = 0; ch < nch; ch++) {
                const int cur = ch & 1;
                if (ch + 1 < nch) load_A(cur ^ 1, hin, (ch + 1) * KC);
                cp_async_commit();
                cp_async_wait1();
                __syncthreads();
#pragma unroll
                for (int kk = 0; kk < KC; kk += 8) {
                    const int kg = ch * KC + kk;
                    wmma::fragment<wmma::matrix_a, 16, 16, 8,
                                   wmma::precision::tf32, wmma::row_major> a;
                    wmma::load_matrix_sync(a, &Asb[cur][(wm * 16) * LDA + kk], LDA);
                    wmma::fragment<wmma::matrix_b, 16, 16, 8,
                                   wmma::precision::tf32, wmma::col_major> b;
                    wmma::load_matrix_sync(b, &Bsm[(wn * 16) * LDB + kg], LDB);
                    wmma::mma_sync(acc, a, b, acc);
                }
                __syncthreads();
            }
        } else {
            load_pre(pre_t);
            cp_async_commit();
            cp_async_wait0();
            __syncthreads();
        }

        // Stage the BT x 64 gate tile
        wmma::store_matrix_sync(&Stage[(wm * 16) * LDS + wn * 16], acc, LDS,
                                wmma::mem_row_major);
        __syncthreads();

        // Epilogue: threads 0..127, each 4 consecutive j of one b-row
        if (tid < 128) {
            const int b = b0 + bl;
            float4 pi = *(const float4*)&PreS[bl * 64 +      jq];
            float4 pf = *(const float4*)&PreS[bl * 64 + 16 + jq];
            float4 pg = *(const float4*)&PreS[bl * 64 + 32 + jq];
            float4 po = *(const float4*)&PreS[bl * 64 + 48 + jq];
            float4 si = *(const float4*)&Stage[bl * LDS +      jq];
            float4 sf = *(const float4*)&Stage[bl * LDS + 16 + jq];
            float4 sg = *(const float4*)&Stage[bl * LDS + 32 + jq];
            float4 so = *(const float4*)&Stage[bl * LDS + 48 + jq];
            float4 hv;
            {
                float gi = si.x + pi.x + breg[0].x;
                float gf = sf.x + pf.x + breg[1].x;
                float gg = sg.x + pg.x + breg[2].x;
                float go = so.x + po.x + breg[3].x;
                float cc = fast_sigmoid(gf) * creg[0] + fast_sigmoid(gi) * fast_tanh(gg);
                creg[0] = cc;  hv.x = fast_sigmoid(go) * fast_tanh(cc);
            }
            {
                float gi = si.y + pi.y + breg[0].y;
                float gf = sf.y + pf.y + breg[1].y;
                float gg = sg.y + pg.y + breg[2].y;
                float go = so.y + po.y + breg[3].y;
                float cc = fast_sigmoid(gf) * creg[1] + fast_sigmoid(gi) * fast_tanh(gg);
                creg[1] = cc;  hv.y = fast_sigmoid(go) * fast_tanh(cc);
            }
            {
                float gi = si.z + pi.z + breg[0].z;
                float gf = sf.z + pf.z + breg[1].z;
                float gg = sg.z + pg.z + breg[2].z;
                float go = so.z + po.z + breg[3].z;
                float cc = fast_sigmoid(gf) * creg[2] + fast_sigmoid(gi) * fast_tanh(gg);
                creg[2] = cc;  hv.z = fast_sigmoid(go) * fast_tanh(cc);
            }
            {
                float gi = si.w + pi.w + breg[0].w;
                float gf = sf.w + pf.w + breg[1].w;
                float gg = sg.w + pg.w + breg[2].w;
                float go = so.w + po.w + breg[3].w;
                float cc = fast_sigmoid(gf) * creg[3] + fast_sigmoid(gi) * fast_tanh(gg);
                creg[3] = cc;  hv.w = fast_sigmoid(go) * fast_tanh(cc);
            }
            const size_t off = (size_t)t * BB * H + (size_t)b * H + jg;
            *(float4*)&hist_t[off] = round4_tf32(hv);   // matmul-input copy
            if (hist != hist_t) *(float4*)&hist[off] = hv;  // raw output copy
        }

        // Grid barrier between steps (skip after last step)
        if (t + 1 < TT) {
            __threadfence();                     // release h writes
            __syncthreads();
            if (tid == 0) {
                atomicAdd(ctr, 1);
                const int target = (t + 1) * nblocks;
                while (*((volatile int*)ctr) < target) __nanosleep(64);
            }
            __syncthreads();
            __threadfence();                     // acquire other blocks' h
        }
    }
}

#define LSTM_SMEM(H) ((64 * ((H) + 4) + 2 * BT * 68 + BT * 68 + BT * 64) * 4)

// ---------------------------------------------------------------------------
// Launch
// ---------------------------------------------------------------------------
extern "C" void kernel_launch(void* const* d_in, const int* in_sizes, int n_in,
                              void* d_out, int out_size)
{
    const float* inp  = (const float*)d_in[0];   // [B,T,IN] flat == [T*B, IN]
    const float* Wih1 = (const float*)d_in[1];   // [4H1, IN]
    const float* Whh1 = (const float*)d_in[2];   // [4H1, H1]
    const float* b1   = (const float*)d_in[3];   // [4H1]
    const float* Wih2 = (const float*)d_in[4];   // [4H2, H1]
    const float* Whh2 = (const float*)d_in[5];   // [4H2, H2]
    const float* b2   = (const float*)d_in[6];   // [4H2]
    float* out = (float*)d_out;                  // flat [T][B][H2]

    float *pre1, *pre2, *y1, *y2t, *inpt, *wih1t, *wih2t;
    int* ctr;
    cudaGetSymbolAddress((void**)&pre1,  g_pre1);
    cudaGetSymbolAddress((void**)&pre2,  g_pre2);
    cudaGetSymbolAddress((void**)&y1,    g_y1);
    cudaGetSymbolAddress((void**)&y2t,   g_y2t);
    cudaGetSymbolAddress((void**)&inpt,  g_inpt);
    cudaGetSymbolAddress((void**)&wih1t, g_wih1t);
    cudaGetSymbolAddress((void**)&wih2t, g_wih2t);
    cudaGetSymbolAddress((void**)&ctr,   g_ctr);

    cudaFuncSetAttribute(gemm_tf32_kernel,
                         cudaFuncAttributeMaxDynamicSharedMemorySize,
                         GEMM_SMEM_BYTES);
    cudaFuncSetAttribute(lstm_layer_kernel<HH1>,
                         cudaFuncAttributeMaxDynamicSharedMemorySize,
                         LSTM_SMEM(HH1));
    cudaFuncSetAttribute(lstm_layer_kernel<HH2>,
                         cudaFuncAttributeMaxDynamicSharedMemorySize,
                         LSTM_SMEM(HH2));

    // RN-round matmul operands to tf32 (once per matrix)
    {
        int n4 = MROWS * INDIM / 4;
        round_tf32_kernel<<<(n4 + 255) / 256, 256>>>((const float4*)inp,
                                                     (float4*)inpt, n4);
        n4 = 4 * HH1 * INDIM / 4;
        round_tf32_kernel<<<(n4 + 255) / 256, 256>>>((const float4*)Wih1,
                                                     (float4*)wih1t, n4);
        n4 = 4 * HH2 * HH1 / 4;
        round_tf32_kernel<<<(n4 + 255) / 256, 256>>>((const float4*)Wih2,
                                                     (float4*)wih2t, n4);
    }

    // Layer 1 input projection: pre1 = inpt @ wih1t^T  (also resets ctr)
    gemm_tf32_kernel<<<dim3(4 * HH1 / 128, MROWS / 128), 256, GEMM_SMEM_BYTES>>>(
        inpt, wih1t, pre1, MROWS, 4 * HH1, INDIM, ctr);

    // Layer 1 recurrence: 64 blocks (all resident); writes tf32 h into y1
    lstm_layer_kernel<HH1><<<dim3(HH1 / 16, BB / BT), 256, LSTM_SMEM(HH1)>>>(
        pre1, Whh1, b1, y1, y1, ctr + 0);

    // Layer 2 input projection: pre2 = y1 @ wih2t^T  (y1 already tf32-rounded;
    // re-resets ctr — ctr[0] dead, ctr[1] reset lands before its consumer)
    gemm_tf32_kernel<<<dim3(4 * HH2 / 128, MROWS / 128), 256, GEMM_SMEM_BYTES>>>(
        y1, wih2t, pre2, MROWS, 4 * HH2, HH1, ctr);

    // Layer 2 recurrence: 128 blocks; raw h -> d_out, tf32 h -> y2t
    lstm_layer_kernel<HH2><<<dim3(HH2 / 16, BB / BT), 256, LSTM_SMEM(HH2)>>>(
        pre2, Whh2, b2, out, y2t, ctr + 1);
}